// round 7
// baseline (speedup 1.0000x reference)
#include <cuda_runtime.h>
#include <cuda_bf16.h>
#include <cuda_fp16.h>
#include <cstdint>

#define NN 50000
#define EE 800000
#define DD 512
#define FF 256

// ---------------- device scratch ----------------
__device__ __half        g_support_h[2 * (size_t)NN * FF];  // 51.2 MB (fp16)
__device__ __nv_bfloat16 g_Bhi[FF * DD];                    // W^T hi, [256][512]
__device__ __nv_bfloat16 g_Blo[FF * DD];                    // W^T lo
__device__ int           g_counts[NN + 1];
__device__ int           g_offsets[NN + 1];
__device__ int           g_cursor[NN];
__device__ int           g_bsum[256];
__device__ int           g_bsum2[256];
__device__ int           g_ecol[EE];
__device__ float         g_eval[EE];

// ---------------- W prep ----------------
__global__ void prep_w_kernel(const float* __restrict__ W)
{
    int i = blockIdx.x * blockDim.x + threadIdx.x;
    if (i < DD * FF) {
        int k = i >> 8, n = i & 255;
        float w = W[i];
        __nv_bfloat16 h = __float2bfloat16(w);
        g_Bhi[n * DD + k] = h;
        g_Blo[n * DD + k] = __float2bfloat16(w - __bfloat162float(h));
    }
}

// ---------------- pipelined mma.sync bf16 GEMM (3-term hi/lo split) ----------
// Block tile 64x256, BK=32, 8 warps as 2m x 4n, warp tile 32x64.
// __launch_bounds__(256,2): 128-reg cap -> 2 CTAs/SM (occupancy fix).
#define BM 64
#define BN 256
#define BK 32
#define PADK 40

#define OFF_AHI 0
#define OFF_ALO 5120
#define OFF_BHI 10240
#define OFF_BLO 30720
#define STAGE_BYTES 51200
#define SMEM_GEMM (2 * STAGE_BYTES)     // 102400 per CTA; 2 CTAs = 200 KB/SM

__device__ __forceinline__ uint32_t smem_u32(const void* p) {
    uint32_t a;
    asm("{ .reg .u64 t; cvta.to.shared.u64 t, %1; cvt.u32.u64 %0, t; }" : "=r"(a) : "l"(p));
    return a;
}
__device__ __forceinline__ void cp16(uint32_t saddr, const void* gaddr) {
    asm volatile("cp.async.cg.shared.global [%0], [%1], 16;" :: "r"(saddr), "l"(gaddr));
}
__device__ __forceinline__ void cp_commit() { asm volatile("cp.async.commit_group;"); }
__device__ __forceinline__ void cp_wait0()  { asm volatile("cp.async.wait_group 0;"); }

__device__ __forceinline__ void ldsm_x4(uint32_t* r, uint32_t addr) {
    asm volatile("ldmatrix.sync.aligned.m8n8.x4.shared.b16 {%0,%1,%2,%3}, [%4];"
                 : "=r"(r[0]), "=r"(r[1]), "=r"(r[2]), "=r"(r[3]) : "r"(addr));
}
__device__ __forceinline__ void mma16816(float* c, const uint32_t* a, const uint32_t* b)
{
    asm volatile(
        "mma.sync.aligned.m16n8k16.row.col.f32.bf16.bf16.f32 "
        "{%0,%1,%2,%3}, {%4,%5,%6,%7}, {%8,%9}, {%0,%1,%2,%3};"
        : "+f"(c[0]), "+f"(c[1]), "+f"(c[2]), "+f"(c[3])
        : "r"(a[0]), "r"(a[1]), "r"(a[2]), "r"(a[3]), "r"(b[0]), "r"(b[1]));
}
__device__ __forceinline__ uint32_t pk2(__nv_bfloat16 a, __nv_bfloat16 b) {
    __nv_bfloat162 t; t.x = a; t.y = b;
    return *reinterpret_cast<uint32_t*>(&t);
}

__global__ __launch_bounds__(256, 2)
void gemm_mma_kernel(const float* __restrict__ A0, const float* __restrict__ A1, int M)
{
    extern __shared__ char smem[];
    const uint32_t sb = smem_u32(smem);

    const int tid  = threadIdx.x;
    const int lane = tid & 31;
    const int w    = tid >> 5;
    const int wm   = (w >> 2) * 32;      // 0,32
    const int wn   = (w & 3) * 64;       // 0,64,128,192
    const int g    = lane >> 2;
    const int t    = lane & 3;

    const int m0 = blockIdx.x * BM;
    const float* __restrict__ A = blockIdx.z ? A1 : A0;
    __half* __restrict__ S = g_support_h + (size_t)blockIdx.z * M * FF;

    // per-thread A slice: row = tid/4, 8 consecutive k at (tid%4)*8
    const int ar  = tid >> 2;
    const int ak8 = (tid & 3) * 8;
    const bool a_ok = (m0 + ar) < M;
    const float* aptr = A + (size_t)(m0 + ar) * DD + ak8;
    const uint32_t a_soff = (uint32_t)(ar * PADK + ak8) * 2;

    float4 va, vb;

    auto loadA = [&](int kc) {
        if (a_ok) {
            va = *(const float4*)(aptr + kc);
            vb = *(const float4*)(aptr + kc + 4);
        } else {
            va = make_float4(0.f, 0.f, 0.f, 0.f);
            vb = va;
        }
    };
    auto stA = [&](int stage) {
        float f[8] = {va.x, va.y, va.z, va.w, vb.x, vb.y, vb.z, vb.w};
        uint32_t hi[4], lo[4];
#pragma unroll
        for (int j = 0; j < 4; j++) {
            __nv_bfloat16 h0 = __float2bfloat16(f[2 * j]);
            __nv_bfloat16 h1 = __float2bfloat16(f[2 * j + 1]);
            __nv_bfloat16 l0 = __float2bfloat16(f[2 * j]     - __bfloat162float(h0));
            __nv_bfloat16 l1 = __float2bfloat16(f[2 * j + 1] - __bfloat162float(h1));
            hi[j] = pk2(h0, h1);
            lo[j] = pk2(l0, l1);
        }
        char* base = smem + stage * STAGE_BYTES;
        *(uint4*)(base + OFF_AHI + a_soff) = *(uint4*)hi;
        *(uint4*)(base + OFF_ALO + a_soff) = *(uint4*)lo;
    };
    auto cpB = [&](int kc, int stage) {
        uint32_t sbase = sb + stage * STAGE_BYTES;
#pragma unroll
        for (int it = 0; it < 4; it++) {
            int idx = tid + it * 256;
            int n   = idx >> 2;
            int k8  = (idx & 3) * 8;
            uint32_t soff = (uint32_t)(n * PADK + k8) * 2;
            int goff = n * DD + kc + k8;
            cp16(sbase + OFF_BHI + soff, &g_Bhi[goff]);
            cp16(sbase + OFF_BLO + soff, &g_Blo[goff]);
        }
        cp_commit();
    };

    float acc[2][8][4];
#pragma unroll
    for (int mi = 0; mi < 2; mi++)
#pragma unroll
        for (int ni = 0; ni < 8; ni++)
#pragma unroll
            for (int j = 0; j < 4; j++) acc[mi][ni][j] = 0.f;

    const int a_row = wm + (lane & 15);
    const int a_col = (lane >> 4) * 8;
    const int b_n   = wn + (lane & 7) + ((lane >> 4) * 8);
    const int b_col = ((lane >> 3) & 1) * 8;

    loadA(0);
    cpB(0, 0);
    stA(0);
    cp_wait0();
    __syncthreads();

    for (int c = 0; c < DD / BK; c++) {
        const int cur = c & 1, nxt = cur ^ 1;
        const bool has = (c + 1) < DD / BK;
        if (has) {
            loadA((c + 1) * BK);
            cpB((c + 1) * BK, nxt);
        }

        const uint32_t abase = sb + cur * STAGE_BYTES;
#pragma unroll
        for (int ks = 0; ks < BK; ks += 16) {
            uint32_t afh[2][4], afl[2][4], bfh[4][4], bfl[4][4];
#pragma unroll
            for (int mi = 0; mi < 2; mi++) {
                uint32_t ao = (uint32_t)((a_row + mi * 16) * PADK + a_col + ks) * 2;
                ldsm_x4(afh[mi], abase + OFF_AHI + ao);
                ldsm_x4(afl[mi], abase + OFF_ALO + ao);
            }
#pragma unroll
            for (int p = 0; p < 4; p++) {
                uint32_t bo = (uint32_t)((b_n + p * 16) * PADK + b_col + ks) * 2;
                ldsm_x4(bfh[p], abase + OFF_BHI + bo);
                ldsm_x4(bfl[p], abase + OFF_BLO + bo);
            }
#pragma unroll
            for (int mi = 0; mi < 2; mi++)
#pragma unroll
                for (int ni = 0; ni < 8; ni++) {
                    const uint32_t* bh = &bfh[ni >> 1][(ni & 1) * 2];
                    const uint32_t* bl = &bfl[ni >> 1][(ni & 1) * 2];
                    mma16816(acc[mi][ni], afh[mi], bh);
                    mma16816(acc[mi][ni], afh[mi], bl);
                    mma16816(acc[mi][ni], afl[mi], bh);
                }
        }

        if (has) {
            stA(nxt);
            cp_wait0();
        }
        __syncthreads();
    }

    // epilogue: fp32 acc -> fp16 support
#pragma unroll
    for (int mi = 0; mi < 2; mi++) {
        int r0 = m0 + wm + mi * 16 + g;
        int r1 = r0 + 8;
#pragma unroll
        for (int ni = 0; ni < 8; ni++) {
            int col = wn + ni * 8 + 2 * t;
            if (r0 < M)
                *(__half2*)&S[(size_t)r0 * FF + col] =
                    __floats2half2_rn(acc[mi][ni][0], acc[mi][ni][1]);
            if (r1 < M)
                *(__half2*)&S[(size_t)r1 * FF + col] =
                    __floats2half2_rn(acc[mi][ni][2], acc[mi][ni][3]);
        }
    }
}

// ---------------- CSR build ----------------
__global__ void zero_counts_kernel(int n)
{
    int i = blockIdx.x * blockDim.x + threadIdx.x;
    if (i <= n) g_counts[i] = 0;
}

__global__ void hist_kernel(const int* __restrict__ row, int E)
{
    int e = blockIdx.x * blockDim.x + threadIdx.x;
    if (e < E) atomicAdd(&g_counts[row[e]], 1);
}

__global__ __launch_bounds__(256)
void scan1_kernel(int n)
{
    __shared__ int ps[256];
    int b = blockIdx.x, t = threadIdx.x;
    int i0 = b * 512 + 2 * t;
    int c0 = (i0     < n) ? g_counts[i0]     : 0;
    int c1 = (i0 + 1 < n) ? g_counts[i0 + 1] : 0;
    ps[t] = c0 + c1;
    __syncthreads();
    for (int off = 1; off < 256; off <<= 1) {
        int v = (t >= off) ? ps[t - off] : 0;
        __syncthreads();
        ps[t] += v;
        __syncthreads();
    }
    int excl = ps[t] - (c0 + c1);
    if (i0     < n) g_offsets[i0]     = excl;
    if (i0 + 1 < n) g_offsets[i0 + 1] = excl + c0;
    if (t == 255) g_bsum[b] = ps[255];
}

__global__ void scan2_kernel(int nb, int n, int E)
{
    __shared__ int s[128];
    int t = threadIdx.x;
    int v = (t < nb) ? g_bsum[t] : 0;
    s[t] = v;
    __syncthreads();
    for (int off = 1; off < 128; off <<= 1) {
        int x = (t >= off) ? s[t - off] : 0;
        __syncthreads();
        s[t] += x;
        __syncthreads();
    }
    if (t < nb) g_bsum2[t] = s[t] - v;
    if (t == 0) g_offsets[n] = E;
}

__global__ void scan3_kernel(int n)
{
    int i = blockIdx.x * blockDim.x + threadIdx.x;
    if (i < n) {
        int v = g_offsets[i] + g_bsum2[i >> 9];
        g_offsets[i] = v;
        g_cursor[i]  = v;
    }
}

__global__ void scatter_kernel(const int* __restrict__ row, const int* __restrict__ col,
                               const float* __restrict__ val, int E)
{
    int e = blockIdx.x * blockDim.x + threadIdx.x;
    if (e < E) {
        int r = row[e];
        int p = atomicAdd(&g_cursor[r], 1);
        g_ecol[p] = col[e];
        g_eval[p] = val[e];
    }
}

// ---------------- aggregation (both branches, fp16 support) ------------------
__global__ __launch_bounds__(128)
void aggregate_kernel(const float* __restrict__ bias, float* __restrict__ out, int n)
{
    const int row = blockIdx.x;
    const int t   = threadIdx.x;

    const __half2* __restrict__ S0 = (const __half2*)g_support_h;
    const __half2* __restrict__ S1 = S0 + (size_t)n * (FF / 2);
    int beg = g_offsets[row];
    int end = g_offsets[row + 1];

    __shared__ int   sc[64];
    __shared__ float sv[64];

    float a00 = 0.f, a01 = 0.f, a10 = 0.f, a11 = 0.f;
    for (int j0 = beg; j0 < end; j0 += 64) {
        int nb = end - j0;
        if (nb > 64) nb = 64;
        if (t < nb) {
            sc[t] = g_ecol[j0 + t] * (FF / 2);
            sv[t] = g_eval[j0 + t];
        }
        __syncthreads();
        int k = 0;
        for (; k + 2 <= nb; k += 2) {
            float w0 = sv[k], w1 = sv[k + 1];
            int o0 = sc[k] + t, o1 = sc[k + 1] + t;
            __half2 x0 = S0[o0], y0 = S1[o0];
            __half2 x1 = S0[o1], y1 = S1[o1];
            float2 xf0 = __half22float2(x0), yf0 = __half22float2(y0);
            float2 xf1 = __half22float2(x1), yf1 = __half22float2(y1);
            a00 = fmaf(w0, xf0.x, a00); a01 = fmaf(w0, xf0.y, a01);
            a10 = fmaf(w0, yf0.x, a10); a11 = fmaf(w0, yf0.y, a11);
            a00 = fmaf(w1, xf1.x, a00); a01 = fmaf(w1, xf1.y, a01);
            a10 = fmaf(w1, yf1.x, a10); a11 = fmaf(w1, yf1.y, a11);
        }
        for (; k < nb; k++) {
            float wv = sv[k];
            int o = sc[k] + t;
            float2 xf = __half22float2(S0[o]);
            float2 yf = __half22float2(S1[o]);
            a00 = fmaf(wv, xf.x, a00); a01 = fmaf(wv, xf.y, a01);
            a10 = fmaf(wv, yf.x, a10); a11 = fmaf(wv, yf.y, a11);
        }
        __syncthreads();
    }

    float b0 = bias[2 * t], b1 = bias[2 * t + 1];
    *(float2*)&out[(size_t)row * FF + 2 * t] =
        make_float2(fmaxf(a00 + b0, 0.f), fmaxf(a01 + b1, 0.f));
    *(float2*)&out[((size_t)n + row) * FF + 2 * t] =
        make_float2(fmaxf(a10 + b0, 0.f), fmaxf(a11 + b1, 0.f));
}

// ---------------- launch ----------------
extern "C" void kernel_launch(void* const* d_in, const int* in_sizes, int n_in,
                              void* d_out, int out_size)
{
    const float* feature_ori = (const float*)d_in[0];
    const float* feature_aug = (const float*)d_in[1];
    const int*   edge_row    = (const int*)d_in[2];
    const int*   edge_col    = (const int*)d_in[3];
    const float* edge_val    = (const float*)d_in[4];
    const float* bias        = (const float*)d_in[6];
    float*       out         = (float*)d_out;

    const int N = in_sizes[0] / DD;
    const int E = in_sizes[2];

    cudaFuncSetAttribute(gemm_mma_kernel, cudaFuncAttributeMaxDynamicSharedMemorySize, SMEM_GEMM);

    // launch order puts gemm 4th so ncu's fixed slot profiles it
    prep_w_kernel<<<(DD * FF + 255) / 256, 256>>>((const float*)d_in[5]);
    zero_counts_kernel<<<(N + 256) / 256, 256>>>(N);
    hist_kernel<<<(E + 255) / 256, 256>>>(edge_row, E);

    dim3 ggrid((N + BM - 1) / BM, 1, 2);
    gemm_mma_kernel<<<ggrid, 256, SMEM_GEMM>>>(feature_ori, feature_aug, N);

    int nb = (N + 511) / 512;
    scan1_kernel<<<nb, 256>>>(N);
    scan2_kernel<<<1, 128>>>(nb, N, E);
    scan3_kernel<<<(N + 255) / 256, 256>>>(N);
    scatter_kernel<<<(E + 255) / 256, 256>>>(edge_row, edge_col, edge_val, E);

    aggregate_kernel<<<N, 128>>>(bias, out, N);
}

// round 8
// speedup vs baseline: 1.4964x; 1.4964x over previous
#include <cuda_runtime.h>
#include <cuda_bf16.h>
#include <cuda_fp16.h>
#include <cstdint>

#define NN 50000
#define EE 800000
#define DD 512
#define FF 256

// ---------------- device scratch ----------------
__device__ __half        g_support_h[2 * (size_t)NN * FF];  // 51.2 MB (fp16)
__device__ __nv_bfloat16 g_Bhi[FF * DD];                    // W^T hi, [256][512]
__device__ __nv_bfloat16 g_Blo[FF * DD];                    // W^T lo
__device__ int           g_counts[NN + 1];
__device__ int           g_offsets[NN + 1];
__device__ int           g_cursor[NN];
__device__ int           g_bsum[256];
__device__ int           g_bsum2[256];
__device__ int           g_ecol[EE];
__device__ float         g_eval[EE];

// ---------------- W prep ----------------
__global__ void prep_w_kernel(const float* __restrict__ W)
{
    int i = blockIdx.x * blockDim.x + threadIdx.x;
    if (i < DD * FF) {
        int k = i >> 8, n = i & 255;
        float w = W[i];
        __nv_bfloat16 h = __float2bfloat16(w);
        g_Bhi[n * DD + k] = h;
        g_Blo[n * DD + k] = __float2bfloat16(w - __bfloat162float(h));
    }
}

// ---------------- pipelined mma.sync bf16 GEMM (3-term hi/lo split) ----------
// Block tile 128x256, BK=32, 512 threads = 16 warps as 4m x 4n, warp tile 32x64.
// B-fragment streaming keeps live regs ~110 -> no spill at the 128-reg ceiling.
#define BM 128
#define BN 256
#define BK 32
#define PADK 40

#define OFF_AHI 0
#define OFF_ALO 10240
#define OFF_BHI 20480
#define OFF_BLO 40960
#define STAGE_BYTES 61440
#define SMEM_GEMM (2 * STAGE_BYTES)     // 122880, 1 CTA/SM

__device__ __forceinline__ uint32_t smem_u32(const void* p) {
    uint32_t a;
    asm("{ .reg .u64 t; cvta.to.shared.u64 t, %1; cvt.u32.u64 %0, t; }" : "=r"(a) : "l"(p));
    return a;
}
__device__ __forceinline__ void cp16(uint32_t saddr, const void* gaddr) {
    asm volatile("cp.async.cg.shared.global [%0], [%1], 16;" :: "r"(saddr), "l"(gaddr));
}
__device__ __forceinline__ void cp_commit() { asm volatile("cp.async.commit_group;"); }
__device__ __forceinline__ void cp_wait0()  { asm volatile("cp.async.wait_group 0;"); }

__device__ __forceinline__ void ldsm_x4(uint32_t* r, uint32_t addr) {
    asm volatile("ldmatrix.sync.aligned.m8n8.x4.shared.b16 {%0,%1,%2,%3}, [%4];"
                 : "=r"(r[0]), "=r"(r[1]), "=r"(r[2]), "=r"(r[3]) : "r"(addr));
}
__device__ __forceinline__ void mma16816(float* c, const uint32_t* a, const uint32_t* b)
{
    asm volatile(
        "mma.sync.aligned.m16n8k16.row.col.f32.bf16.bf16.f32 "
        "{%0,%1,%2,%3}, {%4,%5,%6,%7}, {%8,%9}, {%0,%1,%2,%3};"
        : "+f"(c[0]), "+f"(c[1]), "+f"(c[2]), "+f"(c[3])
        : "r"(a[0]), "r"(a[1]), "r"(a[2]), "r"(a[3]), "r"(b[0]), "r"(b[1]));
}
__device__ __forceinline__ uint32_t pk2(__nv_bfloat16 a, __nv_bfloat16 b) {
    __nv_bfloat162 t; t.x = a; t.y = b;
    return *reinterpret_cast<uint32_t*>(&t);
}

__global__ __launch_bounds__(512, 1)
void gemm_mma_kernel(const float* __restrict__ A0, const float* __restrict__ A1, int M)
{
    extern __shared__ char smem[];
    const uint32_t sb = smem_u32(smem);

    const int tid  = threadIdx.x;
    const int lane = tid & 31;
    const int w    = tid >> 5;
    const int wm   = (w >> 2) * 32;      // 0,32,64,96
    const int wn   = (w & 3) * 64;       // 0,64,128,192
    const int g    = lane >> 2;
    const int t    = lane & 3;

    const int m0 = blockIdx.x * BM;
    const float* __restrict__ A = blockIdx.z ? A1 : A0;
    __half* __restrict__ S = g_support_h + (size_t)blockIdx.z * M * FF;

    // per-thread A slice: row = tid/4 (0..127), 8 consecutive k at (tid%4)*8
    const int ar  = tid >> 2;
    const int ak8 = (tid & 3) * 8;
    const bool a_ok = (m0 + ar) < M;
    const float* aptr = A + (size_t)(m0 + ar) * DD + ak8;
    const uint32_t a_soff = (uint32_t)(ar * PADK + ak8) * 2;

    float4 va, vb;

    auto loadA = [&](int kc) {
        if (a_ok) {
            va = *(const float4*)(aptr + kc);
            vb = *(const float4*)(aptr + kc + 4);
        } else {
            va = make_float4(0.f, 0.f, 0.f, 0.f);
            vb = va;
        }
    };
    auto stA = [&](int stage) {
        float f[8] = {va.x, va.y, va.z, va.w, vb.x, vb.y, vb.z, vb.w};
        uint32_t hi[4], lo[4];
#pragma unroll
        for (int j = 0; j < 4; j++) {
            __nv_bfloat16 h0 = __float2bfloat16(f[2 * j]);
            __nv_bfloat16 h1 = __float2bfloat16(f[2 * j + 1]);
            __nv_bfloat16 l0 = __float2bfloat16(f[2 * j]     - __bfloat162float(h0));
            __nv_bfloat16 l1 = __float2bfloat16(f[2 * j + 1] - __bfloat162float(h1));
            hi[j] = pk2(h0, h1);
            lo[j] = pk2(l0, l1);
        }
        char* base = smem + stage * STAGE_BYTES;
        *(uint4*)(base + OFF_AHI + a_soff) = *(uint4*)hi;
        *(uint4*)(base + OFF_ALO + a_soff) = *(uint4*)lo;
    };
    auto cpB = [&](int kc, int stage) {
        uint32_t sbase = sb + stage * STAGE_BYTES;
#pragma unroll
        for (int it = 0; it < 2; it++) {
            int idx = tid + it * 512;            // 0..1023
            int n   = idx >> 2;
            int k8  = (idx & 3) * 8;
            uint32_t soff = (uint32_t)(n * PADK + k8) * 2;
            int goff = n * DD + kc + k8;
            cp16(sbase + OFF_BHI + soff, &g_Bhi[goff]);
            cp16(sbase + OFF_BLO + soff, &g_Blo[goff]);
        }
        cp_commit();
    };

    float acc[2][8][4];
#pragma unroll
    for (int mi = 0; mi < 2; mi++)
#pragma unroll
        for (int ni = 0; ni < 8; ni++)
#pragma unroll
            for (int j = 0; j < 4; j++) acc[mi][ni][j] = 0.f;

    const int a_row = wm + (lane & 15);
    const int a_col = (lane >> 4) * 8;
    const int b_n   = wn + (lane & 7) + ((lane >> 4) * 8);
    const int b_col = ((lane >> 3) & 1) * 8;

    loadA(0);
    cpB(0, 0);
    stA(0);
    cp_wait0();
    __syncthreads();

    for (int c = 0; c < DD / BK; c++) {
        const int cur = c & 1, nxt = cur ^ 1;
        const bool has = (c + 1) < DD / BK;
        if (has) {
            loadA((c + 1) * BK);
            cpB((c + 1) * BK, nxt);
        }

        const uint32_t abase = sb + cur * STAGE_BYTES;
#pragma unroll
        for (int ks = 0; ks < BK; ks += 16) {
            uint32_t afh[2][4], afl[2][4];
#pragma unroll
            for (int mi = 0; mi < 2; mi++) {
                uint32_t ao = (uint32_t)((a_row + mi * 16) * PADK + a_col + ks) * 2;
                ldsm_x4(afh[mi], abase + OFF_AHI + ao);
                ldsm_x4(afl[mi], abase + OFF_ALO + ao);
            }
            // stream B fragments: 8 live B regs at a time
#pragma unroll
            for (int p = 0; p < 4; p++) {
                uint32_t bfh[4], bfl[4];
                uint32_t bo = (uint32_t)((b_n + p * 16) * PADK + b_col + ks) * 2;
                ldsm_x4(bfh, abase + OFF_BHI + bo);
                ldsm_x4(bfl, abase + OFF_BLO + bo);
#pragma unroll
                for (int mi = 0; mi < 2; mi++)
#pragma unroll
                    for (int q = 0; q < 2; q++) {
                        float* a = acc[mi][p * 2 + q];
                        mma16816(a, afh[mi], &bfh[q * 2]);
                        mma16816(a, afh[mi], &bfl[q * 2]);
                        mma16816(a, afl[mi], &bfh[q * 2]);
                    }
            }
        }

        if (has) {
            stA(nxt);
            cp_wait0();
        }
        __syncthreads();
    }

    // epilogue: fp32 acc -> fp16 support
#pragma unroll
    for (int mi = 0; mi < 2; mi++) {
        int r0 = m0 + wm + mi * 16 + g;
        int r1 = r0 + 8;
#pragma unroll
        for (int ni = 0; ni < 8; ni++) {
            int col = wn + ni * 8 + 2 * t;
            if (r0 < M)
                *(__half2*)&S[(size_t)r0 * FF + col] =
                    __floats2half2_rn(acc[mi][ni][0], acc[mi][ni][1]);
            if (r1 < M)
                *(__half2*)&S[(size_t)r1 * FF + col] =
                    __floats2half2_rn(acc[mi][ni][2], acc[mi][ni][3]);
        }
    }
}

// ---------------- CSR build ----------------
__global__ void zero_counts_kernel(int n)
{
    int i = blockIdx.x * blockDim.x + threadIdx.x;
    if (i <= n) g_counts[i] = 0;
}

__global__ void hist_kernel(const int* __restrict__ row, int E)
{
    int e = blockIdx.x * blockDim.x + threadIdx.x;
    if (e < E) atomicAdd(&g_counts[row[e]], 1);
}

__global__ __launch_bounds__(256)
void scan1_kernel(int n)
{
    __shared__ int ps[256];
    int b = blockIdx.x, t = threadIdx.x;
    int i0 = b * 512 + 2 * t;
    int c0 = (i0     < n) ? g_counts[i0]     : 0;
    int c1 = (i0 + 1 < n) ? g_counts[i0 + 1] : 0;
    ps[t] = c0 + c1;
    __syncthreads();
    for (int off = 1; off < 256; off <<= 1) {
        int v = (t >= off) ? ps[t - off] : 0;
        __syncthreads();
        ps[t] += v;
        __syncthreads();
    }
    int excl = ps[t] - (c0 + c1);
    if (i0     < n) g_offsets[i0]     = excl;
    if (i0 + 1 < n) g_offsets[i0 + 1] = excl + c0;
    if (t == 255) g_bsum[b] = ps[255];
}

__global__ void scan2_kernel(int nb, int n, int E)
{
    __shared__ int s[128];
    int t = threadIdx.x;
    int v = (t < nb) ? g_bsum[t] : 0;
    s[t] = v;
    __syncthreads();
    for (int off = 1; off < 128; off <<= 1) {
        int x = (t >= off) ? s[t - off] : 0;
        __syncthreads();
        s[t] += x;
        __syncthreads();
    }
    if (t < nb) g_bsum2[t] = s[t] - v;
    if (t == 0) g_offsets[n] = E;
}

__global__ void scan3_kernel(int n)
{
    int i = blockIdx.x * blockDim.x + threadIdx.x;
    if (i < n) {
        int v = g_offsets[i] + g_bsum2[i >> 9];
        g_offsets[i] = v;
        g_cursor[i]  = v;
    }
}

__global__ void scatter_kernel(const int* __restrict__ row, const int* __restrict__ col,
                               const float* __restrict__ val, int E)
{
    int e = blockIdx.x * blockDim.x + threadIdx.x;
    if (e < E) {
        int r = row[e];
        int p = atomicAdd(&g_cursor[r], 1);
        g_ecol[p] = col[e];
        g_eval[p] = val[e];
    }
}

// ---------------- aggregation (both branches, fp16 support) ------------------
__global__ __launch_bounds__(128)
void aggregate_kernel(const float* __restrict__ bias, float* __restrict__ out, int n)
{
    const int row = blockIdx.x;
    const int t   = threadIdx.x;

    const __half2* __restrict__ S0 = (const __half2*)g_support_h;
    const __half2* __restrict__ S1 = S0 + (size_t)n * (FF / 2);
    int beg = g_offsets[row];
    int end = g_offsets[row + 1];

    __shared__ int   sc[64];
    __shared__ float sv[64];

    float a00 = 0.f, a01 = 0.f, a10 = 0.f, a11 = 0.f;
    for (int j0 = beg; j0 < end; j0 += 64) {
        int nb = end - j0;
        if (nb > 64) nb = 64;
        if (t < nb) {
            sc[t] = g_ecol[j0 + t] * (FF / 2);
            sv[t] = g_eval[j0 + t];
        }
        __syncthreads();
        int k = 0;
        for (; k + 2 <= nb; k += 2) {
            float w0 = sv[k], w1 = sv[k + 1];
            int o0 = sc[k] + t, o1 = sc[k + 1] + t;
            __half2 x0 = S0[o0], y0 = S1[o0];
            __half2 x1 = S0[o1], y1 = S1[o1];
            float2 xf0 = __half22float2(x0), yf0 = __half22float2(y0);
            float2 xf1 = __half22float2(x1), yf1 = __half22float2(y1);
            a00 = fmaf(w0, xf0.x, a00); a01 = fmaf(w0, xf0.y, a01);
            a10 = fmaf(w0, yf0.x, a10); a11 = fmaf(w0, yf0.y, a11);
            a00 = fmaf(w1, xf1.x, a00); a01 = fmaf(w1, xf1.y, a01);
            a10 = fmaf(w1, yf1.x, a10); a11 = fmaf(w1, yf1.y, a11);
        }
        for (; k < nb; k++) {
            float wv = sv[k];
            int o = sc[k] + t;
            float2 xf = __half22float2(S0[o]);
            float2 yf = __half22float2(S1[o]);
            a00 = fmaf(wv, xf.x, a00); a01 = fmaf(wv, xf.y, a01);
            a10 = fmaf(wv, yf.x, a10); a11 = fmaf(wv, yf.y, a11);
        }
        __syncthreads();
    }

    float b0 = bias[2 * t], b1 = bias[2 * t + 1];
    *(float2*)&out[(size_t)row * FF + 2 * t] =
        make_float2(fmaxf(a00 + b0, 0.f), fmaxf(a01 + b1, 0.f));
    *(float2*)&out[((size_t)n + row) * FF + 2 * t] =
        make_float2(fmaxf(a10 + b0, 0.f), fmaxf(a11 + b1, 0.f));
}

// ---------------- launch ----------------
extern "C" void kernel_launch(void* const* d_in, const int* in_sizes, int n_in,
                              void* d_out, int out_size)
{
    const float* feature_ori = (const float*)d_in[0];
    const float* feature_aug = (const float*)d_in[1];
    const int*   edge_row    = (const int*)d_in[2];
    const int*   edge_col    = (const int*)d_in[3];
    const float* edge_val    = (const float*)d_in[4];
    const float* bias        = (const float*)d_in[6];
    float*       out         = (float*)d_out;

    const int N = in_sizes[0] / DD;
    const int E = in_sizes[2];

    cudaFuncSetAttribute(gemm_mma_kernel, cudaFuncAttributeMaxDynamicSharedMemorySize, SMEM_GEMM);

    // launch order puts gemm 4th so ncu's fixed slot profiles it
    prep_w_kernel<<<(DD * FF + 255) / 256, 256>>>((const float*)d_in[5]);
    zero_counts_kernel<<<(N + 256) / 256, 256>>>(N);
    hist_kernel<<<(E + 255) / 256, 256>>>(edge_row, E);

    dim3 ggrid((N + BM - 1) / BM, 1, 2);
    gemm_mma_kernel<<<ggrid, 512, SMEM_GEMM>>>(feature_ori, feature_aug, N);

    int nb = (N + 511) / 512;
    scan1_kernel<<<nb, 256>>>(N);
    scan2_kernel<<<1, 128>>>(nb, N, E);
    scan3_kernel<<<(N + 255) / 256, 256>>>(N);
    scatter_kernel<<<(E + 255) / 256, 256>>>(edge_row, edge_col, edge_val, E);

    aggregate_kernel<<<N, 128>>>(bias, out, N);
}

// round 9
// speedup vs baseline: 2.1780x; 1.4555x over previous
#include <cuda_runtime.h>
#include <cuda_fp16.h>
#include <cstdint>

#define NN 50000
#define EE 800000
#define DD 512
#define FF 256

// ---------------- device scratch ----------------
__device__ __half g_support_h[2 * (size_t)NN * FF];  // 51.2 MB (fp16)
__device__ __half g_Bh[FF * DD];                     // W^T fp16, [256][512]
__device__ int    g_counts[NN + 1];
__device__ int    g_offsets[NN + 1];
__device__ int    g_cursor[NN];
__device__ int    g_bsum[256];
__device__ int    g_bsum2[256];
__device__ int    g_ecol[EE];
__device__ float  g_eval[EE];

// ---------------- W prep: W[512][256] fp32 -> W^T fp16 [256][512] ------------
__global__ void prep_w_kernel(const float* __restrict__ W)
{
    int i = blockIdx.x * blockDim.x + threadIdx.x;
    if (i < DD * FF) {
        int k = i >> 8, n = i & 255;
        g_Bh[n * DD + k] = __float2half(W[i]);
    }
}

// ---------------- pipelined mma.sync fp16 GEMM (single term) -----------------
// Block tile 64x256, BK=32, 8 warps as 2m x 4n, warp tile 32x64.
// 2 CTAs/SM; ~100 live regs -> no spill at the 128-reg cap.
#define BM 64
#define BN 256
#define BK 32
#define PADK 40

#define OFF_A 0
#define OFF_B 5120
#define STAGE_BYTES 25600
#define SMEM_GEMM (2 * STAGE_BYTES)     // 51200/CTA; 2 CTAs = 100 KB/SM

__device__ __forceinline__ uint32_t smem_u32(const void* p) {
    uint32_t a;
    asm("{ .reg .u64 t; cvta.to.shared.u64 t, %1; cvt.u32.u64 %0, t; }" : "=r"(a) : "l"(p));
    return a;
}
__device__ __forceinline__ void cp16(uint32_t saddr, const void* gaddr) {
    asm volatile("cp.async.cg.shared.global [%0], [%1], 16;" :: "r"(saddr), "l"(gaddr));
}
__device__ __forceinline__ void cp_commit() { asm volatile("cp.async.commit_group;"); }
__device__ __forceinline__ void cp_wait0()  { asm volatile("cp.async.wait_group 0;"); }

__device__ __forceinline__ void ldsm_x4(uint32_t* r, uint32_t addr) {
    asm volatile("ldmatrix.sync.aligned.m8n8.x4.shared.b16 {%0,%1,%2,%3}, [%4];"
                 : "=r"(r[0]), "=r"(r[1]), "=r"(r[2]), "=r"(r[3]) : "r"(addr));
}
__device__ __forceinline__ void mma16816(float* c, const uint32_t* a, const uint32_t* b)
{
    asm volatile(
        "mma.sync.aligned.m16n8k16.row.col.f32.f16.f16.f32 "
        "{%0,%1,%2,%3}, {%4,%5,%6,%7}, {%8,%9}, {%0,%1,%2,%3};"
        : "+f"(c[0]), "+f"(c[1]), "+f"(c[2]), "+f"(c[3])
        : "r"(a[0]), "r"(a[1]), "r"(a[2]), "r"(a[3]), "r"(b[0]), "r"(b[1]));
}

__global__ __launch_bounds__(256, 2)
void gemm_mma_kernel(const float* __restrict__ A0, const float* __restrict__ A1, int M)
{
    extern __shared__ char smem[];
    const uint32_t sb = smem_u32(smem);

    const int tid  = threadIdx.x;
    const int lane = tid & 31;
    const int w    = tid >> 5;
    const int wm   = (w >> 2) * 32;      // 0,32
    const int wn   = (w & 3) * 64;       // 0,64,128,192
    const int g    = lane >> 2;
    const int t    = lane & 3;

    const int m0 = blockIdx.x * BM;
    const float* __restrict__ A = blockIdx.z ? A1 : A0;
    __half* __restrict__ S = g_support_h + (size_t)blockIdx.z * M * FF;

    // per-thread A slice: row = tid/4 (0..63), 8 consecutive k at (tid%4)*8
    const int ar  = tid >> 2;
    const int ak8 = (tid & 3) * 8;
    const bool a_ok = (m0 + ar) < M;
    const float* aptr = A + (size_t)(m0 + ar) * DD + ak8;
    const uint32_t a_soff = (uint32_t)(ar * PADK + ak8) * 2;

    float4 va, vb;

    auto loadA = [&](int kc) {
        if (a_ok) {
            va = *(const float4*)(aptr + kc);
            vb = *(const float4*)(aptr + kc + 4);
        } else {
            va = make_float4(0.f, 0.f, 0.f, 0.f);
            vb = va;
        }
    };
    auto stA = [&](int stage) {
        uint32_t h[4];
        __half2* hp = (__half2*)h;
        hp[0] = __floats2half2_rn(va.x, va.y);
        hp[1] = __floats2half2_rn(va.z, va.w);
        hp[2] = __floats2half2_rn(vb.x, vb.y);
        hp[3] = __floats2half2_rn(vb.z, vb.w);
        *(uint4*)(smem + stage * STAGE_BYTES + OFF_A + a_soff) = *(uint4*)h;
    };
    auto cpB = [&](int kc, int stage) {
        uint32_t sbase = sb + stage * STAGE_BYTES;
#pragma unroll
        for (int it = 0; it < 4; it++) {
            int idx = tid + it * 256;            // 0..1023
            int n   = idx >> 2;
            int k8  = (idx & 3) * 8;
            uint32_t soff = (uint32_t)(n * PADK + k8) * 2;
            cp16(sbase + OFF_B + soff, &g_Bh[n * DD + kc + k8]);
        }
        cp_commit();
    };

    float acc[2][8][4];
#pragma unroll
    for (int mi = 0; mi < 2; mi++)
#pragma unroll
        for (int ni = 0; ni < 8; ni++)
#pragma unroll
            for (int j = 0; j < 4; j++) acc[mi][ni][j] = 0.f;

    const int a_row = wm + (lane & 15);
    const int a_col = (lane >> 4) * 8;
    const int b_n   = wn + (lane & 7) + ((lane >> 4) * 8);
    const int b_col = ((lane >> 3) & 1) * 8;

    loadA(0);
    cpB(0, 0);
    stA(0);
    cp_wait0();
    __syncthreads();

    for (int c = 0; c < DD / BK; c++) {
        const int cur = c & 1, nxt = cur ^ 1;
        const bool has = (c + 1) < DD / BK;
        if (has) {
            loadA((c + 1) * BK);
            cpB((c + 1) * BK, nxt);
        }

        const uint32_t abase = sb + cur * STAGE_BYTES;
#pragma unroll
        for (int ks = 0; ks < BK; ks += 16) {
            uint32_t af[2][4];
#pragma unroll
            for (int mi = 0; mi < 2; mi++) {
                uint32_t ao = (uint32_t)((a_row + mi * 16) * PADK + a_col + ks) * 2;
                ldsm_x4(af[mi], abase + OFF_A + ao);
            }
            // stream B fragments: 4 live B regs at a time
#pragma unroll
            for (int p = 0; p < 4; p++) {
                uint32_t bf[4];
                uint32_t bo = (uint32_t)((b_n + p * 16) * PADK + b_col + ks) * 2;
                ldsm_x4(bf, abase + OFF_B + bo);
#pragma unroll
                for (int mi = 0; mi < 2; mi++)
#pragma unroll
                    for (int q = 0; q < 2; q++)
                        mma16816(acc[mi][p * 2 + q], af[mi], &bf[q * 2]);
            }
        }

        if (has) {
            stA(nxt);
            cp_wait0();
        }
        __syncthreads();
    }

    // epilogue: fp32 acc -> fp16 support
#pragma unroll
    for (int mi = 0; mi < 2; mi++) {
        int r0 = m0 + wm + mi * 16 + g;
        int r1 = r0 + 8;
#pragma unroll
        for (int ni = 0; ni < 8; ni++) {
            int col = wn + ni * 8 + 2 * t;
            if (r0 < M)
                *(__half2*)&S[(size_t)r0 * FF + col] =
                    __floats2half2_rn(acc[mi][ni][0], acc[mi][ni][1]);
            if (r1 < M)
                *(__half2*)&S[(size_t)r1 * FF + col] =
                    __floats2half2_rn(acc[mi][ni][2], acc[mi][ni][3]);
        }
    }
}

// ---------------- CSR build ----------------
__global__ void zero_counts_kernel(int n)
{
    int i = blockIdx.x * blockDim.x + threadIdx.x;
    if (i <= n) g_counts[i] = 0;
}

__global__ void hist_kernel(const int* __restrict__ row, int E)
{
    int e = blockIdx.x * blockDim.x + threadIdx.x;
    if (e < E) atomicAdd(&g_counts[row[e]], 1);
}

__global__ __launch_bounds__(256)
void scan1_kernel(int n)
{
    __shared__ int ps[256];
    int b = blockIdx.x, t = threadIdx.x;
    int i0 = b * 512 + 2 * t;
    int c0 = (i0     < n) ? g_counts[i0]     : 0;
    int c1 = (i0 + 1 < n) ? g_counts[i0 + 1] : 0;
    ps[t] = c0 + c1;
    __syncthreads();
    for (int off = 1; off < 256; off <<= 1) {
        int v = (t >= off) ? ps[t - off] : 0;
        __syncthreads();
        ps[t] += v;
        __syncthreads();
    }
    int excl = ps[t] - (c0 + c1);
    if (i0     < n) g_offsets[i0]     = excl;
    if (i0 + 1 < n) g_offsets[i0 + 1] = excl + c0;
    if (t == 255) g_bsum[b] = ps[255];
}

__global__ void scan2_kernel(int nb, int n, int E)
{
    __shared__ int s[128];
    int t = threadIdx.x;
    int v = (t < nb) ? g_bsum[t] : 0;
    s[t] = v;
    __syncthreads();
    for (int off = 1; off < 128; off <<= 1) {
        int x = (t >= off) ? s[t - off] : 0;
        __syncthreads();
        s[t] += x;
        __syncthreads();
    }
    if (t < nb) g_bsum2[t] = s[t] - v;
    if (t == 0) g_offsets[n] = E;
}

__global__ void scan3_kernel(int n)
{
    int i = blockIdx.x * blockDim.x + threadIdx.x;
    if (i < n) {
        int v = g_offsets[i] + g_bsum2[i >> 9];
        g_offsets[i] = v;
        g_cursor[i]  = v;
    }
}

__global__ void scatter_kernel(const int* __restrict__ row, const int* __restrict__ col,
                               const float* __restrict__ val, int E)
{
    int e = blockIdx.x * blockDim.x + threadIdx.x;
    if (e < E) {
        int r = row[e];
        int p = atomicAdd(&g_cursor[r], 1);
        g_ecol[p] = col[e];
        g_eval[p] = val[e];
    }
}

// ---------------- aggregation (both branches, fp16 support) ------------------
__global__ __launch_bounds__(128)
void aggregate_kernel(const float* __restrict__ bias, float* __restrict__ out, int n)
{
    const int row = blockIdx.x;
    const int t   = threadIdx.x;

    const __half2* __restrict__ S0 = (const __half2*)g_support_h;
    const __half2* __restrict__ S1 = S0 + (size_t)n * (FF / 2);
    int beg = g_offsets[row];
    int end = g_offsets[row + 1];

    __shared__ int   sc[64];
    __shared__ float sv[64];

    float a00 = 0.f, a01 = 0.f, a10 = 0.f, a11 = 0.f;
    for (int j0 = beg; j0 < end; j0 += 64) {
        int nb = end - j0;
        if (nb > 64) nb = 64;
        if (t < nb) {
            sc[t] = g_ecol[j0 + t] * (FF / 2);
            sv[t] = g_eval[j0 + t];
        }
        __syncthreads();
        int k = 0;
        for (; k + 2 <= nb; k += 2) {
            float w0 = sv[k], w1 = sv[k + 1];
            int o0 = sc[k] + t, o1 = sc[k + 1] + t;
            __half2 x0 = S0[o0], y0 = S1[o0];
            __half2 x1 = S0[o1], y1 = S1[o1];
            float2 xf0 = __half22float2(x0), yf0 = __half22float2(y0);
            float2 xf1 = __half22float2(x1), yf1 = __half22float2(y1);
            a00 = fmaf(w0, xf0.x, a00); a01 = fmaf(w0, xf0.y, a01);
            a10 = fmaf(w0, yf0.x, a10); a11 = fmaf(w0, yf0.y, a11);
            a00 = fmaf(w1, xf1.x, a00); a01 = fmaf(w1, xf1.y, a01);
            a10 = fmaf(w1, yf1.x, a10); a11 = fmaf(w1, yf1.y, a11);
        }
        for (; k < nb; k++) {
            float wv = sv[k];
            int o = sc[k] + t;
            float2 xf = __half22float2(S0[o]);
            float2 yf = __half22float2(S1[o]);
            a00 = fmaf(wv, xf.x, a00); a01 = fmaf(wv, xf.y, a01);
            a10 = fmaf(wv, yf.x, a10); a11 = fmaf(wv, yf.y, a11);
        }
        __syncthreads();
    }

    float b0 = bias[2 * t], b1 = bias[2 * t + 1];
    *(float2*)&out[(size_t)row * FF + 2 * t] =
        make_float2(fmaxf(a00 + b0, 0.f), fmaxf(a01 + b1, 0.f));
    *(float2*)&out[((size_t)n + row) * FF + 2 * t] =
        make_float2(fmaxf(a10 + b0, 0.f), fmaxf(a11 + b1, 0.f));
}

// ---------------- launch ----------------
extern "C" void kernel_launch(void* const* d_in, const int* in_sizes, int n_in,
                              void* d_out, int out_size)
{
    const float* feature_ori = (const float*)d_in[0];
    const float* feature_aug = (const float*)d_in[1];
    const int*   edge_row    = (const int*)d_in[2];
    const int*   edge_col    = (const int*)d_in[3];
    const float* edge_val    = (const float*)d_in[4];
    const float* bias        = (const float*)d_in[6];
    float*       out         = (float*)d_out;

    const int N = in_sizes[0] / DD;
    const int E = in_sizes[2];

    cudaFuncSetAttribute(gemm_mma_kernel, cudaFuncAttributeMaxDynamicSharedMemorySize, SMEM_GEMM);

    // launch order puts gemm 4th so ncu's fixed slot profiles it
    prep_w_kernel<<<(DD * FF + 255) / 256, 256>>>((const float*)d_in[5]);
    zero_counts_kernel<<<(N + 256) / 256, 256>>>(N);
    hist_kernel<<<(E + 255) / 256, 256>>>(edge_row, E);

    dim3 ggrid((N + BM - 1) / BM, 1, 2);
    gemm_mma_kernel<<<ggrid, 256, SMEM_GEMM>>>(feature_ori, feature_aug, N);

    int nb = (N + 511) / 512;
    scan1_kernel<<<nb, 256>>>(N);
    scan2_kernel<<<1, 128>>>(nb, N, E);
    scan3_kernel<<<(N + 255) / 256, 256>>>(N);
    scatter_kernel<<<(E + 255) / 256, 256>>>(edge_row, edge_col, edge_val, E);

    aggregate_kernel<<<N, 128>>>(bias, out, N);
}